// round 1
// baseline (speedup 1.0000x reference)
#include <cuda_runtime.h>
#include <cstdint>

#define TT 2048
#define DD 512

// 8 row-blocks of partial y sums, [8][T][D] = 32 MB scratch (deterministic reduction)
__device__ float g_part[(size_t)8 * TT * DD];

typedef unsigned long long ull;

__device__ __forceinline__ ull pk2(float lo, float hi) {
    ull r; asm("mov.b64 %0,{%1,%2};" : "=l"(r) : "f"(lo), "f"(hi)); return r;
}
__device__ __forceinline__ void up2(ull x, float& lo, float& hi) {
    asm("mov.b64 {%0,%1},%2;" : "=f"(lo), "=f"(hi) : "l"(x));
}
__device__ __forceinline__ ull f2fma(ull a, ull b, ull c) {
    ull d; asm("fma.rn.f32x2 %0,%1,%2,%3;" : "=l"(d) : "l"(a), "l"(b), "l"(c)); return d;
}
__device__ __forceinline__ ull f2mul(ull a, ull b) {
    ull d; asm("mul.rn.f32x2 %0,%1,%2;" : "=l"(d) : "l"(a), "l"(b)); return d;
}

#define CP16(dst, src) asm volatile("cp.async.cg.shared.global [%0], [%1], 16;\n" :: "r"(dst), "l"(src))
#define CP_COMMIT()    asm volatile("cp.async.commit_group;\n")
#define CP_WAIT2()     asm volatile("cp.async.wait_group 2;\n" ::: "memory")

// ---------------------------------------------------------------------------
// Main recurrence kernel.
// Grid: (16 col-blocks, 8 row-blocks), 256 threads.
// CTA tile: 64 rows x 32 cols of state. Thread: 8 contiguous rows x 1 col,
// state held as 4 f32x2 register pairs.
// Per step: cp.async-staged r/w/k (64-row slice) + v (32-col slice) in smem,
// f32x2 math, in-CTA distributed reduction of the y partial, partial -> g_part.
// ---------------------------------------------------------------------------
__global__ void __launch_bounds__(256, 1) wkv_main(
    const float* __restrict__ r, const float* __restrict__ w,
    const float* __restrict__ k, const float* __restrict__ v,
    const float* __restrict__ init_state, float* __restrict__ state_out)
{
    __shared__ __align__(16) float stage[4][256]; // per stage: r[64] w[64] k[64] v[32] pad
    __shared__ float part[2][8][36];              // pitch 36 -> conflict-free reduce

    const int tid = threadIdx.x;
    const int bx  = blockIdx.x;   // 0..15 col block
    const int by  = blockIdx.y;   // 0..7  row block
    const int tc  = tid & 31;     // col within tile
    const int tr  = tid >> 5;     // row group (== warp id)
    const int b   = bx * 32 + tc; // global column
    const int a0  = by * 64 + tr * 8;

    // ---- cp.async roles: threads 0..47 stage r/w/k (16B each), 48..55 stage v
    const float* cp_src = nullptr;
    int cp_off = 0;
    const bool is_cp = tid < 56;
    if (tid < 48) {
        int vec = tid >> 4;
        const float* base = (vec == 0) ? r : (vec == 1) ? w : k;
        cp_src = base + by * 64 + (tid & 15) * 4;
        cp_off = vec * 64 + (tid & 15) * 4;
    } else if (tid < 56) {
        int q = tid - 48;
        cp_src = v + bx * 32 + q * 4;
        cp_off = 192 + q * 4;
    }
    unsigned dst_addr[4];
#pragma unroll
    for (int s = 0; s < 4; s++)
        dst_addr[s] = (unsigned)__cvta_generic_to_shared(&stage[s][cp_off]);

    // ---- init state: state0[a][b] = init_state[b]
    const float is0 = init_state[b];
    ull s2[4];
    {
        ull iv = pk2(is0, is0);
#pragma unroll
        for (int i = 0; i < 4; i++) s2[i] = iv;
    }

    // ---- prologue: stages 0,1,2 in flight
#pragma unroll
    for (int s = 0; s < 3; s++) {
        if (is_cp) CP16(dst_addr[s], cp_src + (size_t)s * DD);
        CP_COMMIT();
    }
    const float* cp_ptr = is_cp ? (cp_src + (size_t)3 * DD) : nullptr;
    CP_WAIT2();
    __syncthreads();

    // ---- reduction role: warp rw reduces cols rw*4 .. rw*4+3
    const int lane = tid & 31;
    const int ww   = lane & 7;   // which row-group partial this lane reads
    const int cc   = lane >> 3;  // which of the 4 columns
    const int rcol = tr * 4 + cc;
    float* gp = g_part + (size_t)by * TT * DD + (size_t)bx * 32;

    for (int t = 0; t < TT; t++) {
        const int si = t & 3;
        const ull* sb = reinterpret_cast<const ull*>(&stage[si][0]);

        // r/w/k pairs for this thread's 8 rows (broadcast LDS.128 within warp)
        ulonglong2 ra = *reinterpret_cast<const ulonglong2*>(sb + tr * 4);
        ulonglong2 rb = *reinterpret_cast<const ulonglong2*>(sb + tr * 4 + 2);
        ulonglong2 wa = *reinterpret_cast<const ulonglong2*>(sb + 32 + tr * 4);
        ulonglong2 wb = *reinterpret_cast<const ulonglong2*>(sb + 32 + tr * 4 + 2);
        ulonglong2 ka = *reinterpret_cast<const ulonglong2*>(sb + 64 + tr * 4);
        ulonglong2 kb = *reinterpret_cast<const ulonglong2*>(sb + 64 + tr * 4 + 2);

        const float vf = stage[si][192 + tc];
        const ull vv = pk2(vf, vf);

        // y partial = sum_a r[a] * s[a][b]   (over this thread's 8 rows)
        ull p2;
        p2 = f2mul(ra.x, s2[0]);
        p2 = f2fma(ra.y, s2[1], p2);
        p2 = f2fma(rb.x, s2[2], p2);
        p2 = f2fma(rb.y, s2[3], p2);

        // state update: s = w*s + k*v
        s2[0] = f2fma(wa.x, s2[0], f2mul(ka.x, vv));
        s2[1] = f2fma(wa.y, s2[1], f2mul(ka.y, vv));
        s2[2] = f2fma(wb.x, s2[2], f2mul(kb.x, vv));
        s2[3] = f2fma(wb.y, s2[3], f2mul(kb.y, vv));

        float pl, ph; up2(p2, pl, ph);
        part[t & 1][tr][tc] = pl + ph;

        // stage t+3
        if (is_cp && (t + 3) < TT) CP16(dst_addr[(t + 3) & 3], cp_ptr);
        if (is_cp) cp_ptr += DD;
        CP_COMMIT();
        CP_WAIT2();
        __syncthreads();

        // distributed cross-warp reduction: each warp finishes 4 columns
        float val = part[t & 1][ww][rcol];
        val += __shfl_xor_sync(0xffffffffu, val, 1);
        val += __shfl_xor_sync(0xffffffffu, val, 2);
        val += __shfl_xor_sync(0xffffffffu, val, 4);
        if (ww == 0) gp[(size_t)t * DD + rcol] = val;
    }

    // ---- final state write
    if (state_out) {
#pragma unroll
        for (int i = 0; i < 4; i++) {
            float lo, hi; up2(s2[i], lo, hi);
            state_out[(size_t)(a0 + 2 * i)     * DD + b] = lo;
            state_out[(size_t)(a0 + 2 * i + 1) * DD + b] = hi;
        }
    }
}

// ---------------------------------------------------------------------------
// Combine kernel: per time step t, compute ruk_t = sum_a r*u*k, then
// y[t][b] = ruk_t * v[t][b] + sum over the 8 row-block partials.
// Grid: T blocks x 256 threads.
// ---------------------------------------------------------------------------
__global__ void __launch_bounds__(256) wkv_combine(
    const float* __restrict__ r, const float* __restrict__ k,
    const float* __restrict__ u, const float* __restrict__ v,
    float* __restrict__ y)
{
    const int t = blockIdx.x;
    const int tid = threadIdx.x;
    __shared__ float red[8];

    const float* rt = r + (size_t)t * DD;
    const float* kt = k + (size_t)t * DD;

    float p = rt[tid] * u[tid] * kt[tid]
            + rt[tid + 256] * u[tid + 256] * kt[tid + 256];
#pragma unroll
    for (int m = 16; m >= 1; m >>= 1) p += __shfl_xor_sync(0xffffffffu, p, m);
    if ((tid & 31) == 0) red[tid >> 5] = p;
    __syncthreads();

    float ruk = 0.f;
#pragma unroll
    for (int g = 0; g < 8; g++) ruk += red[g];

#pragma unroll
    for (int j = tid; j < DD; j += 256) {
        float acc = ruk * v[(size_t)t * DD + j];
#pragma unroll
        for (int g = 0; g < 8; g++)
            acc += g_part[(size_t)g * TT * DD + (size_t)t * DD + j];
        y[(size_t)t * DD + j] = acc;
    }
}

// ---------------------------------------------------------------------------
extern "C" void kernel_launch(void* const* d_in, const int* in_sizes, int n_in,
                              void* d_out, int out_size) {
    const float* r          = (const float*)d_in[0];
    const float* w          = (const float*)d_in[1];
    const float* k          = (const float*)d_in[2];
    const float* v          = (const float*)d_in[3];
    const float* init_state = (const float*)d_in[4];
    const float* u          = (const float*)d_in[5];
    float* out = (float*)d_out;

    const int NTD = TT * DD;   // 1048576
    const int NDD = DD * DD;   // 262144

    float* y  = nullptr;
    float* st = nullptr;
    if (out_size >= NTD) {
        y = out;
        if (out_size >= NTD + NDD) st = out + NTD;
    } else if (out_size == NDD) {
        st = out;
    }

    wkv_main<<<dim3(16, 8), 256>>>(r, w, k, v, init_state, st);
    if (y) wkv_combine<<<TT, 256>>>(r, k, u, v, y);
}

// round 2
// speedup vs baseline: 1.7739x; 1.7739x over previous
#include <cuda_runtime.h>
#include <cstdint>

#define TT 2048
#define DD 512
#define STEPS 8
#define NBLK (TT / STEPS)   // 256
#define NSTG 3
#define STEP_F 224          // floats per step in a stage: r64 w64 k64 v32
#define STAGE_B (STEPS * STEP_F * 4)  // bytes per stage buffer = 7168

// 8 row-blocks of partial y sums, [8][T][D] = 32 MB scratch (deterministic reduction)
__device__ float g_part[(size_t)8 * TT * DD];

typedef unsigned long long ull;

__device__ __forceinline__ ull pk2(float lo, float hi) {
    ull r; asm("mov.b64 %0,{%1,%2};" : "=l"(r) : "f"(lo), "f"(hi)); return r;
}
__device__ __forceinline__ void up2(ull x, float& lo, float& hi) {
    asm("mov.b64 {%0,%1},%2;" : "=f"(lo), "=f"(hi) : "l"(x));
}
__device__ __forceinline__ ull f2fma(ull a, ull b, ull c) {
    ull d; asm("fma.rn.f32x2 %0,%1,%2,%3;" : "=l"(d) : "l"(a), "l"(b), "l"(c)); return d;
}
__device__ __forceinline__ ull f2mul(ull a, ull b) {
    ull d; asm("mul.rn.f32x2 %0,%1,%2;" : "=l"(d) : "l"(a), "l"(b)); return d;
}

#define CP16(dst, src) asm volatile("cp.async.cg.shared.global [%0], [%1], 16;\n" :: "r"(dst), "l"(src))
#define CP_COMMIT()    asm volatile("cp.async.commit_group;\n")
#define CP_WAIT1()     asm volatile("cp.async.wait_group 1;\n" ::: "memory")

// ---------------------------------------------------------------------------
// Main recurrence kernel. Grid: (16 col-blocks, 8 row-blocks), 256 threads.
// CTA tile: 64 rows x 32 cols. Thread: 8 rows x 1 col as 4 f32x2 pairs.
// 8 time steps per loop iteration; ONE __syncthreads per 8 steps.
// ---------------------------------------------------------------------------
__global__ void __launch_bounds__(256, 1) wkv_main(
    const float* __restrict__ r, const float* __restrict__ w,
    const float* __restrict__ k, const float* __restrict__ v,
    const float* __restrict__ init_state, float* __restrict__ state_out)
{
    __shared__ __align__(16) float stage[NSTG][STEPS][STEP_F];
    __shared__ float part[2][STEPS][8][36];   // pitch 36 -> conflict-free

    const int tid = threadIdx.x;
    const int bx  = blockIdx.x;   // 0..15 col block
    const int by  = blockIdx.y;   // 0..7  row block
    const int tc  = tid & 31;     // col within tile
    const int tr  = tid >> 5;     // row group (== warp id)
    const int b   = bx * 32 + tc; // global column
    const int a0  = by * 64 + tr * 8;

    // ---- cp.async roles: 56 roles x 4 step-groups (2 steps each) = 224 threads
    const bool is_cp = tid < 224;
    const float* pA = nullptr; const float* pB = nullptr;
    unsigned offA = 0, offB = 0;
    if (is_cp) {
        const int sgrp = tid / 56;          // 0..3
        const int role = tid - sgrp * 56;   // 0..55
        const int s0 = sgrp * 2, s1 = s0 + 1;
        const float* basep; int off;
        if (role < 48) {
            const int vec = role >> 4;
            basep = ((vec == 0) ? r : (vec == 1) ? w : k) + by * 64 + (role & 15) * 4;
            off = vec * 64 + (role & 15) * 4;
        } else {
            const int q = role - 48;
            basep = v + bx * 32 + q * 4;
            off = 192 + q * 4;
        }
        pA = basep + (size_t)s0 * DD;
        pB = basep + (size_t)s1 * DD;
        const unsigned st0 = (unsigned)__cvta_generic_to_shared(&stage[0][0][0]);
        offA = st0 + (unsigned)(s0 * STEP_F + off) * 4u;
        offB = st0 + (unsigned)(s1 * STEP_F + off) * 4u;
    }

    // ---- init state: state0[a][b] = init_state[b]
    const float is0 = init_state[b];
    ull s2[4];
    {
        ull iv = pk2(is0, is0);
#pragma unroll
        for (int i = 0; i < 4; i++) s2[i] = iv;
    }

    // ---- prologue: stage blocks 0 and 1
    if (is_cp) { CP16(offA, pA); CP16(offB, pB); pA += STEPS * DD; pB += STEPS * DD; }
    CP_COMMIT();
    if (is_cp) { CP16(offA + STAGE_B, pA); CP16(offB + STAGE_B, pB); pA += STEPS * DD; pB += STEPS * DD; }
    CP_COMMIT();
    CP_WAIT1();
    __syncthreads();

    // reduction role: warp tr reduces cols tr*4 .. tr*4+3 for all 8 steps
    const int lane = tid & 31;
    const int ww   = lane & 7;
    const int cc   = lane >> 3;
    const int rcol = tr * 4 + cc;
    float* gp = g_part + (size_t)by * TT * DD + (size_t)bx * 32;

    int gOff  = 0;             // byte offset of compute buffer
    unsigned giOff = 2 * STAGE_B;  // byte offset of next issue buffer

    for (int blk = 0; blk < NBLK; blk++) {
        const int p = blk & 1;
        const char* sgb = (const char*)stage + gOff;

#pragma unroll
        for (int st = 0; st < STEPS; st++) {
            const ull* sb = (const ull*)(sgb + st * (STEP_F * 4));

            ulonglong2 ra = *reinterpret_cast<const ulonglong2*>(sb + tr * 4);
            ulonglong2 rb = *reinterpret_cast<const ulonglong2*>(sb + tr * 4 + 2);
            ulonglong2 wa = *reinterpret_cast<const ulonglong2*>(sb + 32 + tr * 4);
            ulonglong2 wb = *reinterpret_cast<const ulonglong2*>(sb + 32 + tr * 4 + 2);
            ulonglong2 ka = *reinterpret_cast<const ulonglong2*>(sb + 64 + tr * 4);
            ulonglong2 kb = *reinterpret_cast<const ulonglong2*>(sb + 64 + tr * 4 + 2);
            const float vf = ((const float*)sb)[192 + tc];
            const ull vv = pk2(vf, vf);

            // y partial = sum over 8 rows of r[a]*state[a][b]
            ull p2;
            p2 = f2mul(ra.x, s2[0]);
            p2 = f2fma(ra.y, s2[1], p2);
            p2 = f2fma(rb.x, s2[2], p2);
            p2 = f2fma(rb.y, s2[3], p2);

            // state update: s = w*s + k*v
            s2[0] = f2fma(wa.x, s2[0], f2mul(ka.x, vv));
            s2[1] = f2fma(wa.y, s2[1], f2mul(ka.y, vv));
            s2[2] = f2fma(wb.x, s2[2], f2mul(kb.x, vv));
            s2[3] = f2fma(wb.y, s2[3], f2mul(kb.y, vv));

            float pl, ph; up2(p2, pl, ph);
            part[p][st][tr][tc] = pl + ph;
        }

        // stage block blk+2
        if (is_cp && (blk + 2) < NBLK) {
            CP16(offA + giOff, pA); CP16(offB + giOff, pB);
            pA += STEPS * DD; pB += STEPS * DD;
        }
        CP_COMMIT();
        CP_WAIT1();
        __syncthreads();

        // distributed cross-warp reduction: 8 steps x 4 cols per warp
        float vals[STEPS];
#pragma unroll
        for (int st = 0; st < STEPS; st++) vals[st] = part[p][st][ww][rcol];
#pragma unroll
        for (int m = 1; m <= 4; m <<= 1)
#pragma unroll
            for (int st = 0; st < STEPS; st++)
                vals[st] += __shfl_xor_sync(0xffffffffu, vals[st], m);
        if (ww == 0) {
            const size_t t0 = (size_t)blk * STEPS;
#pragma unroll
            for (int st = 0; st < STEPS; st++)
                gp[(t0 + st) * DD + rcol] = vals[st];
        }

        gOff  = (gOff  == (NSTG - 1) * STAGE_B) ? 0 : gOff  + STAGE_B;
        giOff = (giOff == (NSTG - 1) * STAGE_B) ? 0 : giOff + STAGE_B;
    }

    // ---- final state write
    if (state_out) {
#pragma unroll
        for (int i = 0; i < 4; i++) {
            float lo, hi; up2(s2[i], lo, hi);
            state_out[(size_t)(a0 + 2 * i)     * DD + b] = lo;
            state_out[(size_t)(a0 + 2 * i + 1) * DD + b] = hi;
        }
    }
}

// ---------------------------------------------------------------------------
// Combine: y[t][b] = (sum_a r*u*k)*v[t][b] + sum of 8 row-block partials.
// ---------------------------------------------------------------------------
__global__ void __launch_bounds__(256) wkv_combine(
    const float* __restrict__ r, const float* __restrict__ k,
    const float* __restrict__ u, const float* __restrict__ v,
    float* __restrict__ y)
{
    const int t = blockIdx.x;
    const int tid = threadIdx.x;
    __shared__ float red[8];

    const float* rt = r + (size_t)t * DD;
    const float* kt = k + (size_t)t * DD;

    float p = rt[tid] * u[tid] * kt[tid]
            + rt[tid + 256] * u[tid + 256] * kt[tid + 256];
#pragma unroll
    for (int m = 16; m >= 1; m >>= 1) p += __shfl_xor_sync(0xffffffffu, p, m);
    if ((tid & 31) == 0) red[tid >> 5] = p;
    __syncthreads();

    float ruk = 0.f;
#pragma unroll
    for (int g = 0; g < 8; g++) ruk += red[g];

#pragma unroll
    for (int j = tid; j < DD; j += 256) {
        float acc = ruk * v[(size_t)t * DD + j];
#pragma unroll
        for (int g = 0; g < 8; g++)
            acc += g_part[(size_t)g * TT * DD + (size_t)t * DD + j];
        y[(size_t)t * DD + j] = acc;
    }
}

// ---------------------------------------------------------------------------
extern "C" void kernel_launch(void* const* d_in, const int* in_sizes, int n_in,
                              void* d_out, int out_size) {
    const float* r          = (const float*)d_in[0];
    const float* w          = (const float*)d_in[1];
    const float* k          = (const float*)d_in[2];
    const float* v          = (const float*)d_in[3];
    const float* init_state = (const float*)d_in[4];
    const float* u          = (const float*)d_in[5];
    float* out = (float*)d_out;

    const int NTD = TT * DD;   // 1048576
    const int NDD = DD * DD;   // 262144

    float* y  = nullptr;
    float* st = nullptr;
    if (out_size >= NTD) {
        y = out;
        if (out_size >= NTD + NDD) st = out + NTD;
    } else if (out_size == NDD) {
        st = out;
    }

    wkv_main<<<dim3(16, 8), 256>>>(r, w, k, v, init_state, st);
    if (y) wkv_combine<<<TT, 256>>>(r, k, u, v, y);
}

// round 3
// speedup vs baseline: 1.8861x; 1.0633x over previous
#include <cuda_runtime.h>
#include <cstdint>

#define TT 2048
#define DD 512
#define STEPS 8
#define NBLK (TT / STEPS)   // 256
#define NSTG 3
#define STEP_F 224          // floats per step in a stage: r64 w64 k64 v32
#define STAGE_B (STEPS * STEP_F * 4)  // bytes per stage buffer = 7168

// 8 row-blocks of partial y sums, [8][T][D] = 32 MB scratch (deterministic reduction)
__device__ float g_part[(size_t)8 * TT * DD];

typedef unsigned long long ull;

__device__ __forceinline__ ull pk2(float lo, float hi) {
    ull r; asm("mov.b64 %0,{%1,%2};" : "=l"(r) : "f"(lo), "f"(hi)); return r;
}
__device__ __forceinline__ void up2(ull x, float& lo, float& hi) {
    asm("mov.b64 {%0,%1},%2;" : "=f"(lo), "=f"(hi) : "l"(x));
}
__device__ __forceinline__ ull f2fma(ull a, ull b, ull c) {
    ull d; asm("fma.rn.f32x2 %0,%1,%2,%3;" : "=l"(d) : "l"(a), "l"(b), "l"(c)); return d;
}
__device__ __forceinline__ ull f2mul(ull a, ull b) {
    ull d; asm("mul.rn.f32x2 %0,%1,%2;" : "=l"(d) : "l"(a), "l"(b)); return d;
}

#define CP16(dst, src) asm volatile("cp.async.cg.shared.global [%0], [%1], 16;\n" :: "r"(dst), "l"(src))
#define CP_COMMIT()    asm volatile("cp.async.commit_group;\n")
#define CP_WAIT1()     asm volatile("cp.async.wait_group 1;\n" ::: "memory")

// ---------------------------------------------------------------------------
// Main recurrence kernel. Grid: (16 col-blocks, 8 row-blocks), 256 threads.
// CTA tile: 64 rows x 32 cols. NEW warp layout: warp wid owns cols
// [wid*4, wid*4+4) and ALL 64 rows; lane = rg*4 + c (rg in 0..7, c in 0..3),
// thread = 8 rows x 1 col as 4 f32x2 pairs. The y row-sum is 3 warp-local
// SHFL.XORs -> no smem partials, no barrier coupling. ONE __syncthreads per
// 8 steps, guarding only the cp.async stage ring.
// ---------------------------------------------------------------------------
__global__ void __launch_bounds__(256, 1) wkv_main(
    const float* __restrict__ r, const float* __restrict__ w,
    const float* __restrict__ k, const float* __restrict__ v,
    const float* __restrict__ init_state, float* __restrict__ state_out)
{
    __shared__ __align__(16) float stage[NSTG][STEPS][STEP_F];

    const int tid  = threadIdx.x;
    const int bx   = blockIdx.x;   // 0..15 col block
    const int by   = blockIdx.y;   // 0..7  row block
    const int wid  = tid >> 5;     // warp id (0..7) -> col group
    const int lane = tid & 31;
    const int c    = lane & 3;     // col within warp group
    const int rg   = lane >> 2;    // row group (0..7), 8 rows each
    const int b    = bx * 32 + wid * 4 + c;  // global column
    const int a0   = by * 64 + rg * 8;       // first global row

    // ---- cp.async roles: 56 roles x 4 step-groups (2 steps each) = 224 threads
    const bool is_cp = tid < 224;
    const float* pA = nullptr; const float* pB = nullptr;
    unsigned offA = 0, offB = 0;
    if (is_cp) {
        const int sgrp = tid / 56;          // 0..3
        const int role = tid - sgrp * 56;   // 0..55
        const int s0 = sgrp * 2, s1 = s0 + 1;
        const float* basep; int off;
        if (role < 48) {
            const int vec = role >> 4;
            basep = ((vec == 0) ? r : (vec == 1) ? w : k) + by * 64 + (role & 15) * 4;
            off = vec * 64 + (role & 15) * 4;
        } else {
            const int q = role - 48;
            basep = v + bx * 32 + q * 4;
            off = 192 + q * 4;
        }
        pA = basep + (size_t)s0 * DD;
        pB = basep + (size_t)s1 * DD;
        const unsigned st0 = (unsigned)__cvta_generic_to_shared(&stage[0][0][0]);
        offA = st0 + (unsigned)(s0 * STEP_F + off) * 4u;
        offB = st0 + (unsigned)(s1 * STEP_F + off) * 4u;
    }

    // ---- init state: state0[a][b] = init_state[b]
    const float is0 = init_state[b];
    ull s2[4];
    {
        ull iv = pk2(is0, is0);
#pragma unroll
        for (int i = 0; i < 4; i++) s2[i] = iv;
    }

    // ---- prologue: stage blocks 0 and 1
    if (is_cp) { CP16(offA, pA); CP16(offB, pB); pA += STEPS * DD; pB += STEPS * DD; }
    CP_COMMIT();
    if (is_cp) { CP16(offA + STAGE_B, pA); CP16(offB + STAGE_B, pB); pA += STEPS * DD; pB += STEPS * DD; }
    CP_COMMIT();
    CP_WAIT1();
    __syncthreads();

    // output pointer for this lane's column partial (lanes 0..3 write)
    float* gp = g_part + (size_t)by * TT * DD + (size_t)bx * 32 + wid * 4 + c;
    const int vidx = 192 + wid * 4 + c;

    int gOff  = 0;                 // byte offset of compute buffer
    unsigned giOff = 2 * STAGE_B;  // byte offset of next issue buffer

    for (int blk = 0; blk < NBLK; blk++) {
        const char* sgb = (const char*)stage + gOff;
        float vals[STEPS];

#pragma unroll
        for (int st = 0; st < STEPS; st++) {
            const ull* sb = (const ull*)(sgb + st * (STEP_F * 4));

            ulonglong2 ra = *reinterpret_cast<const ulonglong2*>(sb + rg * 4);
            ulonglong2 rb = *reinterpret_cast<const ulonglong2*>(sb + rg * 4 + 2);
            ulonglong2 wa = *reinterpret_cast<const ulonglong2*>(sb + 32 + rg * 4);
            ulonglong2 wb = *reinterpret_cast<const ulonglong2*>(sb + 32 + rg * 4 + 2);
            ulonglong2 ka = *reinterpret_cast<const ulonglong2*>(sb + 64 + rg * 4);
            ulonglong2 kb = *reinterpret_cast<const ulonglong2*>(sb + 64 + rg * 4 + 2);
            const float vf = ((const float*)sb)[vidx];
            const ull vv = pk2(vf, vf);

            // y partial = sum over this thread's 8 rows of r[a]*state[a][b]
            ull p2;
            p2 = f2mul(ra.x, s2[0]);
            p2 = f2fma(ra.y, s2[1], p2);
            p2 = f2fma(rb.x, s2[2], p2);
            p2 = f2fma(rb.y, s2[3], p2);

            // state update: s = w*s + k*v
            s2[0] = f2fma(wa.x, s2[0], f2mul(ka.x, vv));
            s2[1] = f2fma(wa.y, s2[1], f2mul(ka.y, vv));
            s2[2] = f2fma(wb.x, s2[2], f2mul(kb.x, vv));
            s2[3] = f2fma(wb.y, s2[3], f2mul(kb.y, vv));

            float pl, ph; up2(p2, pl, ph);
            float val = pl + ph;
            // warp-local reduction over the 8 row groups (lane = rg*4 + c)
            val += __shfl_xor_sync(0xffffffffu, val, 4);
            val += __shfl_xor_sync(0xffffffffu, val, 8);
            val += __shfl_xor_sync(0xffffffffu, val, 16);
            vals[st] = val;
        }

        // lanes 0..3 (rg==0) store the 8 per-step column partials
        if (rg == 0) {
            const size_t t0 = (size_t)blk * STEPS;
#pragma unroll
            for (int st = 0; st < STEPS; st++)
                gp[(t0 + st) * DD] = vals[st];
        }

        // stage block blk+2
        if (is_cp && (blk + 2) < NBLK) {
            CP16(offA + giOff, pA); CP16(offB + giOff, pB);
            pA += STEPS * DD; pB += STEPS * DD;
        }
        CP_COMMIT();
        CP_WAIT1();
        __syncthreads();

        gOff  = (gOff  == (NSTG - 1) * STAGE_B) ? 0 : gOff  + STAGE_B;
        giOff = (giOff == (NSTG - 1) * STAGE_B) ? 0 : giOff + STAGE_B;
    }

    // ---- final state write
    if (state_out) {
#pragma unroll
        for (int i = 0; i < 4; i++) {
            float lo, hi; up2(s2[i], lo, hi);
            state_out[(size_t)(a0 + 2 * i)     * DD + b] = lo;
            state_out[(size_t)(a0 + 2 * i + 1) * DD + b] = hi;
        }
    }
}

// ---------------------------------------------------------------------------
// Combine: y[t][b] = (sum_a r*u*k)*v[t][b] + sum of 8 row-block partials.
// float2-vectorized: 256 threads cover 512 cols as 256 float2s.
// ---------------------------------------------------------------------------
__global__ void __launch_bounds__(256) wkv_combine(
    const float* __restrict__ r, const float* __restrict__ k,
    const float* __restrict__ u, const float* __restrict__ v,
    float* __restrict__ y)
{
    const int t = blockIdx.x;
    const int tid = threadIdx.x;
    __shared__ float red[8];

    const float* rt = r + (size_t)t * DD;
    const float* kt = k + (size_t)t * DD;

    float p = rt[tid] * u[tid] * kt[tid]
            + rt[tid + 256] * u[tid + 256] * kt[tid + 256];
#pragma unroll
    for (int m = 16; m >= 1; m >>= 1) p += __shfl_xor_sync(0xffffffffu, p, m);
    if ((tid & 31) == 0) red[tid >> 5] = p;
    __syncthreads();

    float ruk = 0.f;
#pragma unroll
    for (int g = 0; g < 8; g++) ruk += red[g];

    const float2* v2 = (const float2*)(v + (size_t)t * DD);
    float2* y2 = (float2*)(y + (size_t)t * DD);
    float2 vv = v2[tid];
    float2 acc; acc.x = ruk * vv.x; acc.y = ruk * vv.y;
#pragma unroll
    for (int g = 0; g < 8; g++) {
        const float2* gp2 = (const float2*)(g_part + (size_t)g * TT * DD + (size_t)t * DD);
        float2 pv = gp2[tid];
        acc.x += pv.x; acc.y += pv.y;
    }
    y2[tid] = acc;
}

// ---------------------------------------------------------------------------
extern "C" void kernel_launch(void* const* d_in, const int* in_sizes, int n_in,
                              void* d_out, int out_size) {
    const float* r          = (const float*)d_in[0];
    const float* w          = (const float*)d_in[1];
    const float* k          = (const float*)d_in[2];
    const float* v          = (const float*)d_in[3];
    const float* init_state = (const float*)d_in[4];
    const float* u          = (const float*)d_in[5];
    float* out = (float*)d_out;

    const int NTD = TT * DD;   // 1048576
    const int NDD = DD * DD;   // 262144

    float* y  = nullptr;
    float* st = nullptr;
    if (out_size >= NTD) {
        y = out;
        if (out_size >= NTD + NDD) st = out + NTD;
    } else if (out_size == NDD) {
        st = out;
    }

    wkv_main<<<dim3(16, 8), 256>>>(r, w, k, v, init_state, st);
    if (y) wkv_combine<<<TT, 256>>>(r, k, u, v, y);
}

// round 4
// speedup vs baseline: 2.1136x; 1.1206x over previous
#include <cuda_runtime.h>
#include <cstdint>

#define TT 2048
#define DD 512
#define STEPS 8
#define NBLK (TT / STEPS)   // 256
#define NSTG 3
#define STEP_F 224          // floats per step in a stage: r64 w64 k64 v32
#define STAGE_B (STEPS * STEP_F * 4)  // bytes per stage buffer = 7168
#define PPITCH 65           // part[] col pitch (floats): conflict-free R/W

// 8 row-blocks of partial y sums, [8][T][D] = 32 MB scratch (deterministic reduction)
__device__ float g_part[(size_t)8 * TT * DD];

typedef unsigned long long ull;

__device__ __forceinline__ ull pk2(float lo, float hi) {
    ull r; asm("mov.b64 %0,{%1,%2};" : "=l"(r) : "f"(lo), "f"(hi)); return r;
}
__device__ __forceinline__ void up2(ull x, float& lo, float& hi) {
    asm("mov.b64 {%0,%1},%2;" : "=f"(lo), "=f"(hi) : "l"(x));
}
__device__ __forceinline__ ull f2fma(ull a, ull b, ull c) {
    ull d; asm("fma.rn.f32x2 %0,%1,%2,%3;" : "=l"(d) : "l"(a), "l"(b), "l"(c)); return d;
}
__device__ __forceinline__ ull f2mul(ull a, ull b) {
    ull d; asm("mul.rn.f32x2 %0,%1,%2;" : "=l"(d) : "l"(a), "l"(b)); return d;
}

#define CP16(dst, src) asm volatile("cp.async.cg.shared.global [%0], [%1], 16;\n" :: "r"(dst), "l"(src))
#define CP_COMMIT()    asm volatile("cp.async.commit_group;\n")
#define CP_WAIT1()     asm volatile("cp.async.wait_group 1;\n" ::: "memory")

// ---------------------------------------------------------------------------
// Main recurrence kernel. Grid: (16 col-blocks, 8 row-blocks), 256 threads.
// CTA tile: 64 rows x 32 cols. Warp wid owns cols [wid*4, wid*4+4), all 64
// rows; lane = rg*4 + c. Thread: 8 rows x 1 col as 4 f32x2 pairs.
// Per 8-step block: vals[8] accumulated in regs, ONE batched conflict-free
// smem reduction (8 STS.32 + 8 LDS.32 + coalesced STG), ONE __syncthreads.
// No shuffles anywhere in the hot loop.
// ---------------------------------------------------------------------------
__global__ void __launch_bounds__(256, 1) wkv_main(
    const float* __restrict__ r, const float* __restrict__ w,
    const float* __restrict__ k, const float* __restrict__ v,
    const float* __restrict__ init_state, float* __restrict__ state_out)
{
    __shared__ __align__(16) float stage[NSTG][STEPS][STEP_F];
    __shared__ float part[2][32 * PPITCH];   // [parity][col*65 + rg*8 + st]

    const int tid  = threadIdx.x;
    const int bx   = blockIdx.x;   // 0..15 col block
    const int by   = blockIdx.y;   // 0..7  row block
    const int wid  = tid >> 5;     // warp id (0..7) -> col group
    const int lane = tid & 31;
    const int c    = lane & 3;     // col within warp group
    const int rg   = lane >> 2;    // row group (0..7), 8 rows each
    const int col32 = wid * 4 + c;           // col within CTA tile
    const int b    = bx * 32 + col32;        // global column
    const int a0   = by * 64 + rg * 8;       // first global row

    // ---- cp.async roles: 56 roles x 4 step-groups (2 steps each) = 224 threads
    const bool is_cp = tid < 224;
    const float* pA = nullptr; const float* pB = nullptr;
    unsigned offA = 0, offB = 0;
    if (is_cp) {
        const int sgrp = tid / 56;          // 0..3
        const int role = tid - sgrp * 56;   // 0..55
        const int s0 = sgrp * 2, s1 = s0 + 1;
        const float* basep; int off;
        if (role < 48) {
            const int vec = role >> 4;
            basep = ((vec == 0) ? r : (vec == 1) ? w : k) + by * 64 + (role & 15) * 4;
            off = vec * 64 + (role & 15) * 4;
        } else {
            const int q = role - 48;
            basep = v + bx * 32 + q * 4;
            off = 192 + q * 4;
        }
        pA = basep + (size_t)s0 * DD;
        pB = basep + (size_t)s1 * DD;
        const unsigned st0 = (unsigned)__cvta_generic_to_shared(&stage[0][0][0]);
        offA = st0 + (unsigned)(s0 * STEP_F + off) * 4u;
        offB = st0 + (unsigned)(s1 * STEP_F + off) * 4u;
    }

    // ---- init state: state0[a][b] = init_state[b]
    const float is0 = init_state[b];
    ull s2[4];
    {
        ull iv = pk2(is0, is0);
#pragma unroll
        for (int i = 0; i < 4; i++) s2[i] = iv;
    }

    // ---- prologue: stage blocks 0 and 1
    if (is_cp) { CP16(offA, pA); CP16(offB, pB); pA += STEPS * DD; pB += STEPS * DD; }
    CP_COMMIT();
    if (is_cp) { CP16(offA + STAGE_B, pA); CP16(offB + STAGE_B, pB); pA += STEPS * DD; pB += STEPS * DD; }
    CP_COMMIT();
    CP_WAIT1();
    __syncthreads();

    // writer base: part[p] + col32*65 + rg*8
    const int wbase = col32 * PPITCH + rg * 8;
    // reader role: st = wid, col = lane
    const int rbase = lane * PPITCH + wid;   // + rg*8 while reading
    float* gpr = g_part + (size_t)by * TT * DD + (size_t)bx * 32 + lane; // + t*DD
    const int vidx = 192 + col32;

    int gOff  = 0;                 // byte offset of compute buffer
    unsigned giOff = 2 * STAGE_B;  // byte offset of next issue buffer

    for (int blk = 0; blk < NBLK; blk++) {
        const int p = blk & 1;
        const char* sgb = (const char*)stage + gOff;
        float vals[STEPS];

#pragma unroll
        for (int st = 0; st < STEPS; st++) {
            const ull* sb = (const ull*)(sgb + st * (STEP_F * 4));

            ulonglong2 ra = *reinterpret_cast<const ulonglong2*>(sb + rg * 4);
            ulonglong2 rb = *reinterpret_cast<const ulonglong2*>(sb + rg * 4 + 2);
            ulonglong2 wa = *reinterpret_cast<const ulonglong2*>(sb + 32 + rg * 4);
            ulonglong2 wb = *reinterpret_cast<const ulonglong2*>(sb + 32 + rg * 4 + 2);
            ulonglong2 ka = *reinterpret_cast<const ulonglong2*>(sb + 64 + rg * 4);
            ulonglong2 kb = *reinterpret_cast<const ulonglong2*>(sb + 64 + rg * 4 + 2);
            const float vf = ((const float*)sb)[vidx];
            const ull vv = pk2(vf, vf);

            // y partial = sum over this thread's 8 rows of r[a]*state[a][b]
            ull p2;
            p2 = f2mul(ra.x, s2[0]);
            p2 = f2fma(ra.y, s2[1], p2);
            p2 = f2fma(rb.x, s2[2], p2);
            p2 = f2fma(rb.y, s2[3], p2);

            // state update: s = w*s + k*v
            s2[0] = f2fma(wa.x, s2[0], f2mul(ka.x, vv));
            s2[1] = f2fma(wa.y, s2[1], f2mul(ka.y, vv));
            s2[2] = f2fma(wb.x, s2[2], f2mul(kb.x, vv));
            s2[3] = f2fma(wb.y, s2[3], f2mul(kb.y, vv));

            float pl, ph; up2(p2, pl, ph);
            vals[st] = pl + ph;
        }

        // batched partial write: 8 STS.32, conflict-free (pitch 65)
        {
            float* pw = &part[p][wbase];
#pragma unroll
            for (int st = 0; st < STEPS; st++) pw[st] = vals[st];
        }

        // stage block blk+2
        if (is_cp && (blk + 2) < NBLK) {
            CP16(offA + giOff, pA); CP16(offB + giOff, pB);
            pA += STEPS * DD; pB += STEPS * DD;
        }
        CP_COMMIT();
        CP_WAIT1();
        __syncthreads();

        // batched reduction: thread (st=wid, col=lane) sums 8 row-group
        // partials; conflict-free reads, coalesced 128B g_part store.
        {
            const float* pr = &part[p][rbase];
            float acc = pr[0];
#pragma unroll
            for (int g = 1; g < 8; g++) acc += pr[g * 8];
            gpr[(size_t)(blk * STEPS + wid) * DD] = acc;
        }

        gOff  = (gOff  == (NSTG - 1) * STAGE_B) ? 0 : gOff  + STAGE_B;
        giOff = (giOff == (NSTG - 1) * STAGE_B) ? 0 : giOff + STAGE_B;
    }

    // ---- final state write
    if (state_out) {
#pragma unroll
        for (int i = 0; i < 4; i++) {
            float lo, hi; up2(s2[i], lo, hi);
            state_out[(size_t)(a0 + 2 * i)     * DD + b] = lo;
            state_out[(size_t)(a0 + 2 * i + 1) * DD + b] = hi;
        }
    }
}

// ---------------------------------------------------------------------------
// Combine: y[t][b] = (sum_a r*u*k)*v[t][b] + sum of 8 row-block partials.
// float2-vectorized: 256 threads cover 512 cols as 256 float2s.
// ---------------------------------------------------------------------------
__global__ void __launch_bounds__(256) wkv_combine(
    const float* __restrict__ r, const float* __restrict__ k,
    const float* __restrict__ u, const float* __restrict__ v,
    float* __restrict__ y)
{
    const int t = blockIdx.x;
    const int tid = threadIdx.x;
    __shared__ float red[8];

    const float* rt = r + (size_t)t * DD;
    const float* kt = k + (size_t)t * DD;

    float p = rt[tid] * u[tid] * kt[tid]
            + rt[tid + 256] * u[tid + 256] * kt[tid + 256];
#pragma unroll
    for (int m = 16; m >= 1; m >>= 1) p += __shfl_xor_sync(0xffffffffu, p, m);
    if ((tid & 31) == 0) red[tid >> 5] = p;
    __syncthreads();

    float ruk = 0.f;
#pragma unroll
    for (int g = 0; g < 8; g++) ruk += red[g];

    const float2* v2 = (const float2*)(v + (size_t)t * DD);
    float2* y2 = (float2*)(y + (size_t)t * DD);
    float2 vv = v2[tid];
    float2 acc; acc.x = ruk * vv.x; acc.y = ruk * vv.y;
#pragma unroll
    for (int g = 0; g < 8; g++) {
        const float2* gp2 = (const float2*)(g_part + (size_t)g * TT * DD + (size_t)t * DD);
        float2 pv = gp2[tid];
        acc.x += pv.x; acc.y += pv.y;
    }
    y2[tid] = acc;
}

// ---------------------------------------------------------------------------
extern "C" void kernel_launch(void* const* d_in, const int* in_sizes, int n_in,
                              void* d_out, int out_size) {
    const float* r          = (const float*)d_in[0];
    const float* w          = (const float*)d_in[1];
    const float* k          = (const float*)d_in[2];
    const float* v          = (const float*)d_in[3];
    const float* init_state = (const float*)d_in[4];
    const float* u          = (const float*)d_in[5];
    float* out = (float*)d_out;

    const int NTD = TT * DD;   // 1048576
    const int NDD = DD * DD;   // 262144

    float* y  = nullptr;
    float* st = nullptr;
    if (out_size >= NTD) {
        y = out;
        if (out_size >= NTD + NDD) st = out + NTD;
    } else if (out_size == NDD) {
        st = out;
    }

    wkv_main<<<dim3(16, 8), 256>>>(r, w, k, v, init_state, st);
    if (y) wkv_combine<<<TT, 256>>>(r, k, u, v, y);
}